// round 6
// baseline (speedup 1.0000x reference)
#include <cuda_runtime.h>

#define NB 32     // batch
#define H  512    // hidden
#define NL 2      // layers
#define NT 20     // text_max_len
#define NV 10000  // vocab
#define NS 49     // spatial
#define NBLK 148  // persistent grid (== SM count, all co-resident)

typedef unsigned long long u64;
typedef unsigned int u32;

// ---------------- device scratch ----------------
__device__ __align__(16) float g_keysT[NB][NS][H];
__device__ __align__(16) float g_valsT[NB][NS][H];
__device__ __align__(16) float g_hA[NL][NB][H];   // h into LSTM (attention-updated)
__device__ __align__(16) float g_hB[NL][NB][H];   // h out of LSTM
__device__ __align__(16) float g_cS[NL][NB][H];   // cell state (block-private)
__device__ __align__(16) float g_q[NL * NB][H];
__device__ __align__(16) float g_attn[NL * NB][H];
__device__ u64 g_amax[NB];                        // packed argmax (key<<32)|~v
__device__ int g_actr;                            // attn-done counter
__device__ int g_barctr;                          // grid barrier
__device__ volatile int g_bargen;

// ---------------- helpers ----------------
__device__ __forceinline__ void fma2(u64& d, u64 a, u64 b) {
    asm("fma.rn.f32x2 %0, %1, %2, %0;" : "+l"(d) : "l"(a), "l"(b));
}
__device__ __forceinline__ float sum2(u64 a) {
    float lo, hi; asm("mov.b64 {%0,%1}, %2;" : "=f"(lo), "=f"(hi) : "l"(a));
    return lo + hi;
}
__device__ __forceinline__ float sigmf(float x) { return 1.f / (1.f + expf(-x)); }
__device__ __forceinline__ float wredsum(float v) {
    #pragma unroll
    for (int o = 16; o; o >>= 1) v += __shfl_xor_sync(0xffffffffu, v, o);
    return v;
}
__device__ __forceinline__ u64 packlv(float f, int v) {
    u32 u = __float_as_uint(f);
    u = (u & 0x80000000u) ? ~u : (u | 0x80000000u);
    return ((u64)u << 32) | (u32)(~v);
}

// grid barrier: sense-reversing, safe at grid<=NBLK co-resident blocks
__device__ __forceinline__ void gridbar() {
    __threadfence();
    __syncthreads();
    if (threadIdx.x == 0) {
        int gen = g_bargen;
        if (atomicAdd(&g_barctr, 1) == NBLK - 1) {
            g_barctr = 0;
            __threadfence();
            g_bargen = gen + 1;
        } else {
            while (g_bargen == gen) __nanosleep(64);
        }
    }
    __syncthreads();
}

// ---------------- prologue: keys/values + state init ----------------
__global__ __launch_bounds__(256) void kPrepState(
    const float* __restrict__ chan, const float* __restrict__ Wk, const float* __restrict__ bk,
    const float* __restrict__ Wv, const float* __restrict__ bv,
    const float* __restrict__ pooled, const int* __restrict__ sos)
{
    if ((int)blockIdx.x < 64) {
        int idx = blockIdx.x * 256 + threadIdx.x;    // 16384 = 32*512
        int b = idx >> 9, d = idx & 511;
        float cr[NS];
        const float* cp = chan + ((size_t)b * H + d) * NS;
        #pragma unroll
        for (int j = 0; j < NS; j++) cr[j] = cp[j];
        for (int s = 0; s < NS; s++) {
            float ak = bk[s], av = bv[s];
            #pragma unroll
            for (int j = 0; j < NS; j++) {
                ak += cr[j] * Wk[s * NS + j];
                av += cr[j] * Wv[s * NS + j];
            }
            g_keysT[b][s][d] = tanhf(ak);
            g_valsT[b][s][d] = tanhf(av);
        }
    } else {
        int idx = ((int)blockIdx.x - 64) * 256 + threadIdx.x;  // 32768
        int l = idx >> 14, b = (idx >> 9) & 31, k = idx & 511;
        float p = pooled[b * H + k];
        g_hA[l][b][k] = p;
        g_cS[l][b][k] = p;
        if (idx < NB) g_amax[idx] = (u64)(u32)(~(u32)(*sos));
    }
}

// ---------------- phase: LSTM layer (blocks 0..127) ----------------
__device__ __forceinline__ void phaseLstm(
    unsigned char* SMUc, int bid, int tid, int layer, int xg,
    const float* __restrict__ embed,
    const float* __restrict__ Wih, const float* __restrict__ Whh,
    const float* __restrict__ bih, const float* __restrict__ bhh)
{
    __shared__ int stokL[NB];
    if (layer == 1) {   // safe window: tokens consumed in L0, argmax written in LQ
        if (bid == 128 && tid < NB) g_amax[tid] = 0ull;
        if (bid == 129 && tid == 0) g_actr = 0;
    }
    if (bid >= 128) return;
    u64* wt = (u64*)SMUc;                     // [2][16][33]
    u64* xt = wt + 1056;                      // [2][32][33]
    float* gpart = (float*)(xt + 2112);       // [8][16][32]
    int wid = tid >> 5, lane = tid & 31;
    int rpair = lane >> 2, bq = lane & 3;
    int u0 = bid * 4;

    if (xg) {
        if (tid < NB) stokL[tid] = (int)(~(u32)__ldcg(&g_amax[tid]));
        __syncthreads();
    }

    size_t wbase = (size_t)layer * 4 * H * H;
    u64 accA[8], accB[8];
    #pragma unroll
    for (int j = 0; j < 8; j++) { accA[j] = 0ull; accB[j] = 0ull; }

    int s_rl = tid >> 4, s_wc = tid & 15;
    int grow = (s_rl >> 2) * H + u0 + (s_rl & 3);
    ulonglong2 wreg, xreg[2];

    #define LSTM_PF(c) {                                                         \
        int koff = ((c) & 7) * 64;                                               \
        const float* Wm = (((c) < 8) ? Wih : Whh) + wbase;                       \
        wreg = *(const ulonglong2*)(Wm + (size_t)grow * H + koff + s_wc * 4);    \
        _Pragma("unroll")                                                        \
        for (int j = 0; j < 2; j++) {                                            \
            int idx = tid + j * 256;                                             \
            int bb = idx >> 4, xc = idx & 15;                                    \
            int k = koff + xc * 4;                                               \
            if ((c) >= 8)  xreg[j] = __ldcg((const ulonglong2*)&g_hA[layer][bb][k]); \
            else if (xg)   xreg[j] = *(const ulonglong2*)(embed + (size_t)stokL[bb] * H + k); \
            else           xreg[j] = __ldcg((const ulonglong2*)&g_hB[0][bb][k]); \
        } }

    LSTM_PF(0);
    for (int c = 0; c < 16; c++) {
        int buf = c & 1;
        wt[(buf * 16 + s_rl) * 33 + s_wc * 2]     = wreg.x;
        wt[(buf * 16 + s_rl) * 33 + s_wc * 2 + 1] = wreg.y;
        #pragma unroll
        for (int j = 0; j < 2; j++) {
            int idx = tid + j * 256;
            int bb = idx >> 4, xc = idx & 15;
            xt[(buf * 32 + bb) * 33 + xc * 2]     = xreg[j].x;
            xt[(buf * 32 + bb) * 33 + xc * 2 + 1] = xreg[j].y;
        }
        __syncthreads();
        if (c < 15) LSTM_PF(c + 1);
        #pragma unroll
        for (int ss = 0; ss < 4; ss++) {
            int s = wid * 4 + ss;
            u64 w0 = wt[(buf * 16 + rpair) * 33 + s];
            u64 w1 = wt[(buf * 16 + rpair + 8) * 33 + s];
            #pragma unroll
            for (int j = 0; j < 8; j++) {
                u64 xv = xt[(buf * 32 + bq * 8 + j) * 33 + s];
                fma2(accA[j], xv, w0);
                fma2(accB[j], xv, w1);
            }
        }
        __syncthreads();
    }
    #undef LSTM_PF
    #pragma unroll
    for (int j = 0; j < 8; j++) {
        gpart[(wid * 16 + rpair) * 32 + bq * 8 + j]     = sum2(accA[j]);
        gpart[(wid * 16 + rpair + 8) * 32 + bq * 8 + j] = sum2(accB[j]);
    }
    __syncthreads();
    for (int o = tid; o < 512; o += 256) {
        int r = o >> 5, bb = o & 31;
        float s = 0.f;
        #pragma unroll
        for (int w = 0; w < 8; w++) s += gpart[(w * 16 + r) * 32 + bb];
        gpart[r * 32 + bb] = s;
    }
    __syncthreads();
    if (tid < 128) {
        int bb = tid & 31, uu = (tid >> 5) & 3;
        int u = u0 + uu;
        int bo = layer * 4 * H;
        float gi = gpart[uu * 32 + bb]        + bih[bo + u]       + bhh[bo + u];
        float gf = gpart[(4 + uu) * 32 + bb]  + bih[bo + H + u]   + bhh[bo + H + u];
        float gg = gpart[(8 + uu) * 32 + bb]  + bih[bo + 2*H + u] + bhh[bo + 2*H + u];
        float go = gpart[(12 + uu) * 32 + bb] + bih[bo + 3*H + u] + bhh[bo + 3*H + u];
        float c0 = g_cS[layer][bb][u];
        float cn = sigmf(gf) * c0 + sigmf(gi) * tanhf(gg);
        g_cS[layer][bb][u] = cn;
        g_hB[layer][bb][u] = sigmf(go) * tanhf(cn);
    }
}

// ---------------- phase: logits (blocks 32..110) + q (blocks 0..31 if doq) ----
__device__ __forceinline__ void phaseLQ(
    unsigned char* SMUc, u64* sam, int bid, int tid, int xg,
    const float* __restrict__ embed,
    const float* __restrict__ projW, const float* __restrict__ projb,
    const float* __restrict__ Wq, const float* __restrict__ bq_,
    float* __restrict__ res, int tout, int doamax, int doq)
{
    __shared__ int stokQ[NB];
    int wid = tid >> 5, lane = tid & 31;
    int rpair = lane >> 2, bqi = lane & 3;
    if (bid >= 32 && bid < 111) {
        // ------------ logits role ------------
        u64* wtL = (u64*)SMUc;                // [2][128][17]
        u64* xtL = wtL + 4352;                // [2][32][17]
        if (doamax && tid < NB) sam[tid] = 0ull;
        if (xg) {
            if (tid < NB) stokQ[tid] = (int)(~(u32)__ldcg(&g_amax[tid]));
            __syncthreads();
        }
        int vbase = (bid - 32) * 128;
        u64 accA[8], accB[8];
        #pragma unroll
        for (int j = 0; j < 8; j++) { accA[j] = 0ull; accB[j] = 0ull; }

        ulonglong2 wreg[4], xreg;
        #define LOG_PF(c) {                                                      \
            int koff = (c) * 32;                                                 \
            _Pragma("unroll")                                                    \
            for (int j = 0; j < 4; j++) {                                        \
                int idx = tid + j * 256;                                         \
                int rl = idx >> 3, wc = idx & 7;                                 \
                int v = vbase + rl; if (v > NV - 1) v = NV - 1;                  \
                wreg[j] = *(const ulonglong2*)(projW + (size_t)v * H + koff + wc * 4); \
            }                                                                    \
            { int bb = tid >> 3, xc = tid & 7;                                   \
              int k = koff + xc * 4;                                             \
              if (xg) xreg = *(const ulonglong2*)(embed + (size_t)stokQ[bb] * H + k); \
              else    xreg = __ldcg((const ulonglong2*)&g_hB[1][bb][k]);         \
            } }

        LOG_PF(0);
        for (int c = 0; c < 16; c++) {
            int buf = c & 1;
            #pragma unroll
            for (int j = 0; j < 4; j++) {
                int idx = tid + j * 256;
                int rl = idx >> 3, wc = idx & 7;
                wtL[(buf * 128 + rl) * 17 + wc * 2]     = wreg[j].x;
                wtL[(buf * 128 + rl) * 17 + wc * 2 + 1] = wreg[j].y;
            }
            { int bb = tid >> 3, xc = tid & 7;
              xtL[(buf * 32 + bb) * 17 + xc * 2]     = xreg.x;
              xtL[(buf * 32 + bb) * 17 + xc * 2 + 1] = xreg.y; }
            __syncthreads();
            if (c < 15) LOG_PF(c + 1);
            #pragma unroll
            for (int s = 0; s < 16; s++) {
                u64 w0 = wtL[(buf * 128 + wid * 16 + rpair) * 17 + s];
                u64 w1 = wtL[(buf * 128 + wid * 16 + rpair + 8) * 17 + s];
                #pragma unroll
                for (int j = 0; j < 8; j++) {
                    u64 xv = xtL[(buf * 32 + bqi * 8 + j) * 17 + s];
                    fma2(accA[j], xv, w0);
                    fma2(accB[j], xv, w1);
                }
            }
            __syncthreads();
        }
        #undef LOG_PF
        int v0 = vbase + wid * 16 + rpair;
        int v1 = v0 + 8;
        float pb0 = (v0 < NV) ? projb[v0] : 0.f;
        float pb1 = (v1 < NV) ? projb[v1] : 0.f;
        #pragma unroll
        for (int j = 0; j < 8; j++) {
            int b = bqi * 8 + j;
            float l0 = sum2(accA[j]) + pb0;
            float l1 = sum2(accB[j]) + pb1;
            if (v0 < NV) res[(size_t)b * NV * NT + (size_t)v0 * NT + tout] = l0;
            if (v1 < NV) res[(size_t)b * NV * NT + (size_t)v1 * NT + tout] = l1;
            if (doamax) {
                u64 best = 0ull;
                if (v0 < NV) best = packlv(l0, v0);
                if (v1 < NV) { u64 p1 = packlv(l1, v1); if (p1 > best) best = p1; }
                atomicMax(&sam[b], best);
            }
        }
        if (doamax) {
            __syncthreads();
            if (tid < NB) atomicMax(&g_amax[tid], sam[tid]);
        }
    } else if (doq && bid < 32) {
        // ------------ q GEMM role: 16 rows x 64 cols x k512 ------------
        u64* wtQ = (u64*)SMUc;                        // [2][16][17]
        u64* xtQ = wtQ + 544;                         // [2][64][17]
        float* gp = (float*)(xtQ + 2176);             // [4][16][64]
        int u0 = bid * 16;
        int kg = wid >> 1, colg = wid & 1;
        u64 accA[8], accB[8];
        #pragma unroll
        for (int j = 0; j < 8; j++) { accA[j] = 0ull; accB[j] = 0ull; }

        ulonglong2 wreg, xreg[2];
        #define Q_PF(c) {                                                        \
            int koff = (c) * 32;                                                 \
            if (tid < 128) {                                                     \
                int rl = tid >> 3, wc = tid & 7;                                 \
                wreg = *(const ulonglong2*)(Wq + (size_t)(u0 + rl) * H + koff + wc * 4); \
            }                                                                    \
            _Pragma("unroll")                                                    \
            for (int j = 0; j < 2; j++) {                                        \
                int idx = tid + j * 256;                                         \
                int lb = idx >> 3, xc = idx & 7;                                 \
                int k = koff + xc * 4;                                           \
                xreg[j] = __ldcg((const ulonglong2*)&g_hB[lb >> 5][lb & 31][k]); \
            } }

        Q_PF(0);
        for (int c = 0; c < 16; c++) {
            int buf = c & 1;
            if (tid < 128) {
                int rl = tid >> 3, wc = tid & 7;
                wtQ[(buf * 16 + rl) * 17 + wc * 2]     = wreg.x;
                wtQ[(buf * 16 + rl) * 17 + wc * 2 + 1] = wreg.y;
            }
            #pragma unroll
            for (int j = 0; j < 2; j++) {
                int idx = tid + j * 256;
                int lb = idx >> 3, xc = idx & 7;
                xtQ[(buf * 64 + lb) * 17 + xc * 2]     = xreg[j].x;
                xtQ[(buf * 64 + lb) * 17 + xc * 2 + 1] = xreg[j].y;
            }
            __syncthreads();
            if (c < 15) Q_PF(c + 1);
            #pragma unroll
            for (int ss = 0; ss < 4; ss++) {
                int s = kg * 4 + ss;
                u64 w0 = wtQ[(buf * 16 + rpair) * 17 + s];
                u64 w1 = wtQ[(buf * 16 + rpair + 8) * 17 + s];
                #pragma unroll
                for (int j = 0; j < 8; j++) {
                    u64 xv = xtQ[(buf * 64 + colg * 32 + bqi * 8 + j) * 17 + s];
                    fma2(accA[j], xv, w0);
                    fma2(accB[j], xv, w1);
                }
            }
            __syncthreads();
        }
        #undef Q_PF
        #pragma unroll
        for (int j = 0; j < 8; j++) {
            int cl = colg * 32 + bqi * 8 + j;
            gp[(kg * 16 + rpair) * 64 + cl]     = sum2(accA[j]);
            gp[(kg * 16 + rpair + 8) * 64 + cl] = sum2(accB[j]);
        }
        __syncthreads();
        #pragma unroll
        for (int i = 0; i < 4; i++) {
            int o = tid + i * 256;
            int r = o >> 6, cl = o & 63;
            float s = gp[r * 64 + cl] + gp[(16 + r) * 64 + cl]
                    + gp[(32 + r) * 64 + cl] + gp[(48 + r) * 64 + cl];
            int u = u0 + r;
            g_q[cl][u] = tanhf(s + bq_[u]);
        }
    }
}

// ---------------- phase: attn (blocks 0..31) + hatt (blocks 32..47) ----------
__device__ __forceinline__ void phaseAH(
    unsigned char* SMUc, int bid, int tid,
    const float* __restrict__ hattW, const float* __restrict__ hattb)
{
    int wid = tid >> 5, lane = tid & 31;
    if (bid < 32) {
        // ------------ attention role ------------
        float* qs = (float*)SMUc;            // [2][512]
        float* sc = qs + 1024;               // [2][64]
        int b = bid;
        #pragma unroll
        for (int j = 0; j < 4; j++) {
            int idx = tid + j * 256;
            qs[idx] = __ldcg(&g_q[(idx >> 9) * 32 + b][idx & 511]);
        }
        __syncthreads();
        for (int d = wid; d < 2 * NS; d += 8) {
            int s = d >> 1, l = d & 1;
            const float* kr = &g_keysT[b][s][lane * 16];
            const float* qp = qs + l * 512 + lane * 16;
            u64 a = 0;
            #pragma unroll
            for (int t4 = 0; t4 < 4; t4++) {
                ulonglong2 kv = *(const ulonglong2*)(kr + t4 * 4);
                ulonglong2 qv = *(const ulonglong2*)(qp + t4 * 4);
                fma2(a, qv.x, kv.x);
                fma2(a, qv.y, kv.y);
            }
            float sv = wredsum(sum2(a));
            if (lane == 0) sc[l * 64 + s] = sv * (1.f / 7.f);
        }
        __syncthreads();
        if (tid < 2) {
            float* p = sc + tid * 64;
            float m = p[0];
            for (int s = 1; s < NS; s++) m = fmaxf(m, p[s]);
            float sum = 0.f;
            for (int s = 0; s < NS; s++) { float e = expf(p[s] - m); p[s] = e; sum += e; }
            float inv = 1.f / sum;
            for (int s = 0; s < NS; s++) p[s] *= inv;
        }
        __syncthreads();
        {
            int d2 = tid * 2;
            float a00 = 0.f, a01 = 0.f, a10 = 0.f, a11 = 0.f;
            for (int s = 0; s < NS; s++) {
                float2 v = *(const float2*)&g_valsT[b][s][d2];
                float w0 = sc[s], w1 = sc[64 + s];
                a00 += w0 * v.x; a01 += w0 * v.y;
                a10 += w1 * v.x; a11 += w1 * v.y;
            }
            *(float2*)&g_attn[b][d2]      = make_float2(a00, a01);
            *(float2*)&g_attn[32 + b][d2] = make_float2(a10, a11);
        }
        __threadfence();
        __syncthreads();
        if (tid == 0) atomicAdd(&g_actr, 1);
    } else if (bid < 48) {
        // ------------ hatt GEMM role: 32r x 64c x k1024 ------------
        u64* wtH = (u64*)SMUc;                    // [2][32][17]
        u64* xtH = wtH + 1088;                    // [2][64][17]
        float* gp = (float*)(xtH + 2176);         // [2][32][64]
        int u0 = (bid - 32) * 32;
        int rpair = lane >> 2, bqi = lane & 3;
        int kg = wid >> 2, colg = (wid >> 1) & 1, rowg = wid & 1;

        if (tid == 0) {
            while (*(volatile int*)&g_actr < NB) __nanosleep(64);
            __threadfence();
        }
        __syncthreads();

        u64 accA[8], accB[8];
        #pragma unroll
        for (int j = 0; j < 8; j++) { accA[j] = 0ull; accB[j] = 0ull; }

        ulonglong2 wreg, xreg[2];
        #define HT_PF(c) {                                                       \
            int koff = (c) * 32;                                                 \
            { int rl = tid >> 3, wc = tid & 7;                                   \
              wreg = *(const ulonglong2*)(hattW + (size_t)(u0 + rl) * (2 * H) + koff + wc * 4); } \
            _Pragma("unroll")                                                    \
            for (int j = 0; j < 2; j++) {                                        \
                int idx = tid + j * 256;                                         \
                int lb = idx >> 3, xc = idx & 7;                                 \
                int k = koff + xc * 4;                                           \
                if (k < H) xreg[j] = __ldcg((const ulonglong2*)&g_attn[lb][k]);  \
                else       xreg[j] = __ldcg((const ulonglong2*)&g_hB[lb >> 5][lb & 31][k - H]); \
            } }

        HT_PF(0);
        for (int c = 0; c < 32; c++) {
            int buf = c & 1;
            { int rl = tid >> 3, wc = tid & 7;
              wtH[(buf * 32 + rl) * 17 + wc * 2]     = wreg.x;
              wtH[(buf * 32 + rl) * 17 + wc * 2 + 1] = wreg.y; }
            #pragma unroll
            for (int j = 0; j < 2; j++) {
                int idx = tid + j * 256;
                int lb = idx >> 3, xc = idx & 7;
                xtH[(buf * 64 + lb) * 17 + xc * 2]     = xreg[j].x;
                xtH[(buf * 64 + lb) * 17 + xc * 2 + 1] = xreg[j].y;
            }
            __syncthreads();
            if (c < 31) HT_PF(c + 1);
            #pragma unroll
            for (int ss = 0; ss < 8; ss++) {
                int s = kg * 8 + ss;
                u64 w0 = wtH[(buf * 32 + rowg * 16 + rpair) * 17 + s];
                u64 w1 = wtH[(buf * 32 + rowg * 16 + rpair + 8) * 17 + s];
                #pragma unroll
                for (int j = 0; j < 8; j++) {
                    u64 xv = xtH[(buf * 64 + colg * 32 + bqi * 8 + j) * 17 + s];
                    fma2(accA[j], xv, w0);
                    fma2(accB[j], xv, w1);
                }
            }
            __syncthreads();
        }
        #undef HT_PF
        #pragma unroll
        for (int j = 0; j < 8; j++) {
            int cl = colg * 32 + bqi * 8 + j;
            int r0 = rowg * 16 + rpair;
            gp[(kg * 32 + r0) * 64 + cl]     = sum2(accA[j]);
            gp[(kg * 32 + r0 + 8) * 64 + cl] = sum2(accB[j]);
        }
        __syncthreads();
        #pragma unroll
        for (int i = 0; i < 8; i++) {
            int o = tid + i * 256;
            int r = o >> 6, cl = o & 63;
            float s = gp[r * 64 + cl] + gp[(32 + r) * 64 + cl];
            int u = u0 + r;
            g_hA[cl >> 5][cl & 31][u] = tanhf(s + hattb[u]);
        }
    }
}

// ---------------- persistent main kernel ----------------
__global__ __launch_bounds__(256) void kMain(
    const float* __restrict__ embed,
    const float* __restrict__ Wih, const float* __restrict__ Whh,
    const float* __restrict__ bih, const float* __restrict__ bhh,
    const float* __restrict__ projW, const float* __restrict__ projb,
    const float* __restrict__ Wq, const float* __restrict__ bq_,
    const float* __restrict__ hattW, const float* __restrict__ hattb,
    float* __restrict__ res)
{
    __shared__ __align__(16) unsigned char SMU[43520];
    __shared__ u64 sam[NB];
    int bid = blockIdx.x, tid = threadIdx.x;

    // res[:, :, 0] from <SOS> embedding (g_amax holds sos; no argmax, no q)
    phaseLQ(SMU, sam, bid, tid, 1, embed, projW, projb, Wq, bq_, res, 0, 0, 0);
    gridbar();

    for (int t = 0; t < NT - 1; t++) {
        phaseLstm(SMU, bid, tid, 0, 1, embed, Wih, Whh, bih, bhh);
        gridbar();
        phaseLstm(SMU, bid, tid, 1, 0, embed, Wih, Whh, bih, bhh);
        gridbar();
        phaseLQ(SMU, sam, bid, tid, 0, embed, projW, projb, Wq, bq_, res, t + 1, 1, 1);
        if (t < NT - 2) {
            gridbar();
            phaseAH(SMU, bid, tid, hattW, hattb);
            gridbar();
        }
    }
}

// ---------------- launch ----------------
extern "C" void kernel_launch(void* const* d_in, const int* in_sizes, int n_in,
                              void* d_out, int out_size)
{
    const float* chan   = (const float*)d_in[0];
    const float* pooled = (const float*)d_in[1];
    const float* embed  = (const float*)d_in[2];
    const float* Wq     = (const float*)d_in[3];
    const float* bq     = (const float*)d_in[4];
    const float* Wk     = (const float*)d_in[5];
    const float* bk     = (const float*)d_in[6];
    const float* Wv     = (const float*)d_in[7];
    const float* bv     = (const float*)d_in[8];
    const float* Wih    = (const float*)d_in[9];
    const float* Whh    = (const float*)d_in[10];
    const float* bih    = (const float*)d_in[11];
    const float* bhh    = (const float*)d_in[12];
    const float* projW  = (const float*)d_in[13];
    const float* projb  = (const float*)d_in[14];
    const float* hattW  = (const float*)d_in[15];
    const float* hattb  = (const float*)d_in[16];
    const int*   sos    = (const int*)d_in[17];
    float* res = (float*)d_out;

    kPrepState<<<192, 256>>>(chan, Wk, bk, Wv, bv, pooled, sos);
    kMain<<<NBLK, 256>>>(embed, Wih, Whh, bih, bhh, projW, projb,
                         Wq, bq, hattW, hattb, res);
}

// round 7
// speedup vs baseline: 2.2844x; 2.2844x over previous
#include <cuda_runtime.h>

#define NB 32     // batch
#define H  512    // hidden
#define NL 2      // layers
#define NT 20     // text_max_len
#define NV 10000  // vocab
#define NS 49     // spatial
#define NBLK2 128 // kLstm2 grid (co-resident, internal barrier)

typedef unsigned long long u64;
typedef unsigned int u32;

// ---------------- device scratch ----------------
__device__ __align__(16) float g_keysT[NB][NS][H];
__device__ __align__(16) float g_valsT[NB][NS][H];
__device__ __align__(16) float g_hA[NL][NB][H];   // h into LSTM (attention-updated)
__device__ __align__(16) float g_hB[NL][NB][H];   // h out of LSTM
__device__ __align__(16) float g_cS[NL][NB][H];   // cell state
__device__ __align__(16) float g_q[NL * NB][H];
__device__ __align__(16) float g_attn[NL * NB][H];
__device__ u64 g_amax[NB];                        // packed argmax (key<<32)|~v
__device__ int g_qctr, g_attnctr;
__device__ int g_barctr;
__device__ volatile int g_bargen;

// ---------------- helpers ----------------
__device__ __forceinline__ void fma2(u64& d, u64 a, u64 b) {
    asm("fma.rn.f32x2 %0, %1, %2, %0;" : "+l"(d) : "l"(a), "l"(b));
}
__device__ __forceinline__ float sum2(u64 a) {
    float lo, hi; asm("mov.b64 {%0,%1}, %2;" : "=f"(lo), "=f"(hi) : "l"(a));
    return lo + hi;
}
__device__ __forceinline__ float sigmf(float x) { return 1.f / (1.f + expf(-x)); }
__device__ __forceinline__ float wredsum(float v) {
    #pragma unroll
    for (int o = 16; o; o >>= 1) v += __shfl_xor_sync(0xffffffffu, v, o);
    return v;
}
__device__ __forceinline__ u64 packlv(float f, int v) {
    u32 u = __float_as_uint(f);
    u = (u & 0x80000000u) ? ~u : (u | 0x80000000u);
    return ((u64)u << 32) | (u32)(~v);
}
// cp.async: .ca caches in L1 (weights, read-only), .cg bypasses L1 (activations)
__device__ __forceinline__ void cpaCA(void* s, const void* g) {
    asm volatile("cp.async.ca.shared.global [%0], [%1], 16;"
                 :: "r"((u32)__cvta_generic_to_shared(s)), "l"(g));
}
__device__ __forceinline__ void cpaCG(void* s, const void* g) {
    asm volatile("cp.async.cg.shared.global [%0], [%1], 16;"
                 :: "r"((u32)__cvta_generic_to_shared(s)), "l"(g));
}
#define CPC() asm volatile("cp.async.commit_group;")
#define CPW(n) asm volatile("cp.async.wait_group %0;" :: "n"(n))

// grid barrier across NBLK2 co-resident blocks
__device__ __forceinline__ void gridbar128() {
    __threadfence();
    __syncthreads();
    if (threadIdx.x == 0) {
        int gen = g_bargen;
        if (atomicAdd(&g_barctr, 1) == NBLK2 - 1) {
            g_barctr = 0;
            __threadfence();
            g_bargen = gen + 1;
        } else {
            while (g_bargen == gen) __nanosleep(32);
        }
    }
    __syncthreads();
}

// ---------------- prologue: keys/values + state init ----------------
__global__ __launch_bounds__(256) void kPrepState(
    const float* __restrict__ chan, const float* __restrict__ Wk, const float* __restrict__ bk,
    const float* __restrict__ Wv, const float* __restrict__ bv,
    const float* __restrict__ pooled, const int* __restrict__ sos)
{
    if ((int)blockIdx.x < 64) {
        int idx = blockIdx.x * 256 + threadIdx.x;    // 16384 = 32*512
        int b = idx >> 9, d = idx & 511;
        float cr[NS];
        const float* cp = chan + ((size_t)b * H + d) * NS;
        #pragma unroll
        for (int j = 0; j < NS; j++) cr[j] = cp[j];
        for (int s = 0; s < NS; s++) {
            float ak = bk[s], av = bv[s];
            #pragma unroll
            for (int j = 0; j < NS; j++) {
                ak += cr[j] * Wk[s * NS + j];
                av += cr[j] * Wv[s * NS + j];
            }
            g_keysT[b][s][d] = tanhf(ak);
            g_valsT[b][s][d] = tanhf(av);
        }
    } else {
        int idx = ((int)blockIdx.x - 64) * 256 + threadIdx.x;  // 32768
        int l = idx >> 14, b = (idx >> 9) & 31, k = idx & 511;
        float p = pooled[b * H + k];
        g_hA[l][b][k] = p;
        g_cS[l][b][k] = p;
        if (idx < NB) g_amax[idx] = (u64)(u32)(~(u32)(*sos));
        if (idx == NB) { g_qctr = 0; g_attnctr = 0; g_barctr = 0; g_bargen = 0; }
    }
}

// ---------------- kLstm2: both layers, internal grid barrier ----------------
// grid 128 x 256 thr. Block: 16 gate-rows (4 gates x 4 units) x 32 b x k1024.
// cp.async 3-stage pipeline, chunk 64 k. Warps k-split 8-way (4 u64 each).
// Stage: wt 16 rows x 68 stride (4352B) + xt 32 rows x 68 (8704B) = 13056B.
__global__ __launch_bounds__(256) void kLstm2(
    const float* __restrict__ embed,
    const float* __restrict__ Wih, const float* __restrict__ Whh,
    const float* __restrict__ bih, const float* __restrict__ bhh)
{
    __shared__ __align__(16) unsigned char SMU[3 * 13056];
    __shared__ int stok[NB];
    int tid = threadIdx.x, bid = blockIdx.x;
    int wid = tid >> 5, lane = tid & 31;
    int rpair = lane >> 2, bqi = lane & 3;
    int u0 = bid * 4;
    int s_rl = tid >> 4, s_wc = tid & 15;
    int grow = (s_rl >> 2) * H + u0 + (s_rl & 3);   // gate-major weight row

    if (tid < NB) stok[tid] = (int)(~(u32)__ldcg(&g_amax[tid]));
    __syncthreads();

    for (int layer = 0; layer < NL; layer++) {
        size_t wb = (size_t)layer * 4 * H * H;
        u64 accA[8], accB[8];
        #pragma unroll
        for (int j = 0; j < 8; j++) { accA[j] = 0ull; accB[j] = 0ull; }

        auto issue = [&](int c) {
            char* st = (char*)SMU + (c % 3) * 13056;
            int koff = (c & 7) * 64;
            const float* Wm = ((c < 8) ? Wih : Whh) + wb;
            cpaCA(st + s_rl * 272 + s_wc * 16, Wm + (size_t)grow * H + koff + s_wc * 4);
            char* xt = st + 4352;
            #pragma unroll
            for (int j = 0; j < 2; j++) {
                int idx = tid + j * 256;
                int bb = idx >> 4, xc = idx & 15;
                const float* src;
                if (layer == 0) src = (c < 8) ? embed + (size_t)stok[bb] * H : &g_hA[0][bb][0];
                else            src = (c < 8) ? &g_hB[0][bb][0]              : &g_hA[1][bb][0];
                cpaCG(xt + bb * 272 + xc * 16, src + koff + xc * 4);
            }
            CPC();
        };

        issue(0); issue(1);
        for (int c = 0; c < 16; c++) {
            if (c + 2 < 16) issue(c + 2); else CPC();
            CPW(2);
            __syncthreads();
            const float* wtf = (const float*)((char*)SMU + (c % 3) * 13056);
            const float* xtf = wtf + 1088;   // +4352B
            #pragma unroll
            for (int ss = 0; ss < 4; ss++) {
                int s = wid * 4 + ss;
                u64 w0 = *(const u64*)(wtf + rpair * 68 + s * 2);
                u64 w1 = *(const u64*)(wtf + (rpair + 8) * 68 + s * 2);
                #pragma unroll
                for (int j = 0; j < 8; j++) {
                    u64 xv = *(const u64*)(xtf + (4 * j + bqi) * 68 + s * 2);
                    fma2(accA[j], xv, w0);
                    fma2(accB[j], xv, w1);
                }
            }
            __syncthreads();
        }
        CPW(0);
        // deterministic cross-warp k-reduction (alias stage memory)
        float* gpart = (float*)SMU;    // [8][16][32]
        #pragma unroll
        for (int j = 0; j < 8; j++) {
            gpart[(wid * 16 + rpair) * 32 + 4 * j + bqi]       = sum2(accA[j]);
            gpart[(wid * 16 + rpair + 8) * 32 + 4 * j + bqi]   = sum2(accB[j]);
        }
        __syncthreads();
        for (int o = tid; o < 512; o += 256) {
            int r = o >> 5, bb = o & 31;
            float s = 0.f;
            #pragma unroll
            for (int w = 0; w < 8; w++) s += gpart[(w * 16 + r) * 32 + bb];
            gpart[r * 32 + bb] = s;   // each (r,bb) owned by exactly one thread
        }
        __syncthreads();
        if (tid < 128) {
            int bb = tid & 31, uu = (tid >> 5) & 3;
            int u = u0 + uu;
            int bo = layer * 4 * H;
            float gi = gpart[uu * 32 + bb]        + bih[bo + u]       + bhh[bo + u];
            float gf = gpart[(4 + uu) * 32 + bb]  + bih[bo + H + u]   + bhh[bo + H + u];
            float gg = gpart[(8 + uu) * 32 + bb]  + bih[bo + 2*H + u] + bhh[bo + 2*H + u];
            float go = gpart[(12 + uu) * 32 + bb] + bih[bo + 3*H + u] + bhh[bo + 3*H + u];
            float c0 = g_cS[layer][bb][u];
            float cn = sigmf(gf) * c0 + sigmf(gi) * tanhf(gg);
            g_cS[layer][bb][u] = cn;
            g_hB[layer][bb][u] = sigmf(go) * tanhf(cn);
        }
        __syncthreads();
        if (layer == 0) {
            gridbar128();   // L1 consumes g_hB[0] via cp.async.cg (L2-coherent)
            if (bid == 0) { // tokens consumed; reset step state for next kStep
                if (tid < NB)  g_amax[tid] = 0ull;
                if (tid == 32) g_qctr = 0;
                if (tid == 33) g_attnctr = 0;
            }
        }
    }
}

// ---------------- kStep: logits [0,79) || q+hatt [79,111) || attn [111,143) --
// logits: 128 vocab rows x 32 b x k512, cp.async 2-stage chunk 32.
// q:      16 rows x 64 lb x k512 3-stage -> qctr; then hatt h-half (k512..1023),
//         wait attnctr, hatt attn-half (k0..511) -> g_hA.
// attn:   wait qctr; per-b scores/softmax/context for both l -> attnctr.
__global__ __launch_bounds__(256) void kStep(
    int xg, const float* __restrict__ embed,
    const float* __restrict__ projW, const float* __restrict__ projb,
    const float* __restrict__ Wq, const float* __restrict__ bq_,
    const float* __restrict__ hattW, const float* __restrict__ hattb,
    float* __restrict__ res, int tout, int doamax, int doq)
{
    __shared__ __align__(16) unsigned char SMU[46080];
    __shared__ u64 sam[NB];
    __shared__ int stok[NB];
    int tid = threadIdx.x, bid = blockIdx.x;
    int wid = tid >> 5, lane = tid & 31;
    int rpair = lane >> 2, bqi = lane & 3;

    if (bid < 79) {
        // ------------ logits: 2-stage pipeline, stage = 23040B ------------
        if (doamax && tid < NB) sam[tid] = 0ull;
        if (xg && tid < NB) stok[tid] = (int)(~(u32)__ldcg(&g_amax[tid]));
        __syncthreads();
        int vbase = bid * 128;
        u64 accA[8], accB[8];
        #pragma unroll
        for (int j = 0; j < 8; j++) { accA[j] = 0ull; accB[j] = 0ull; }

        auto issue = [&](int c) {
            char* st = (char*)SMU + (c & 1) * 23040;
            int koff = c * 32;
            #pragma unroll
            for (int j = 0; j < 4; j++) {
                int idx = tid + j * 256;
                int rl = idx >> 3, wc = idx & 7;
                int v = vbase + rl; if (v > NV - 1) v = NV - 1;
                cpaCA(st + rl * 144 + wc * 16, projW + (size_t)v * H + koff + wc * 4);
            }
            {
                int bb = tid >> 3, xc = tid & 7;
                const float* src = xg ? embed + (size_t)stok[bb] * H : &g_hB[1][bb][0];
                cpaCG(st + 18432 + bb * 144 + xc * 16, src + koff + xc * 4);
            }
            CPC();
        };

        issue(0);
        for (int c = 0; c < 16; c++) {
            if (c + 1 < 16) issue(c + 1); else CPC();
            CPW(1);
            __syncthreads();
            const float* wtf = (const float*)((char*)SMU + (c & 1) * 23040);
            const float* xtf = wtf + 4608;   // +18432B
            #pragma unroll
            for (int s = 0; s < 16; s++) {
                u64 w0 = *(const u64*)(wtf + (wid * 16 + rpair) * 36 + s * 2);
                u64 w1 = *(const u64*)(wtf + (wid * 16 + rpair + 8) * 36 + s * 2);
                #pragma unroll
                for (int j = 0; j < 8; j++) {
                    u64 xv = *(const u64*)(xtf + (4 * j + bqi) * 36 + s * 2);
                    fma2(accA[j], xv, w0);
                    fma2(accB[j], xv, w1);
                }
            }
            __syncthreads();
        }
        int v0 = vbase + wid * 16 + rpair;
        int v1 = v0 + 8;
        float pb0 = (v0 < NV) ? projb[v0] : 0.f;
        float pb1 = (v1 < NV) ? projb[v1] : 0.f;
        #pragma unroll
        for (int j = 0; j < 8; j++) {
            int b = 4 * j + bqi;
            float l0 = sum2(accA[j]) + pb0;
            float l1 = sum2(accB[j]) + pb1;
            if (v0 < NV) res[(size_t)b * NV * NT + (size_t)v0 * NT + tout] = l0;
            if (v1 < NV) res[(size_t)b * NV * NT + (size_t)v1 * NT + tout] = l1;
            if (doamax) {
                u64 best = 0ull;
                if (v0 < NV) best = packlv(l0, v0);
                if (v1 < NV) { u64 p1 = packlv(l1, v1); if (p1 > best) best = p1; }
                atomicMax(&sam[b], best);
            }
        }
        if (doamax) {
            __syncthreads();
            if (tid < NB) atomicMax(&g_amax[tid], sam[tid]);
        }
    } else if (bid < 111) {
        if (!doq) return;
        // ------------ q GEMM then hatt (16 rows x 64 lb), 3-stage 11520B ----
        int u0 = (bid - 79) * 16;
        int kg = wid >> 1, colg = wid & 1;
        int w_act = tid < 128;
        int q_rl = tid >> 3, q_wc = tid & 7;
        u64 accA[8], accB[8];
        #pragma unroll
        for (int j = 0; j < 8; j++) { accA[j] = 0ull; accB[j] = 0ull; }

        // --- q: W=Wq rows u0.., X=g_hB (lb = l*32+b) ---
        auto issueQ = [&](int c) {
            char* st = (char*)SMU + (c % 3) * 11520;
            int koff = c * 32;
            if (w_act)
                cpaCA(st + q_rl * 144 + q_wc * 16,
                      Wq + (size_t)(u0 + q_rl) * H + koff + q_wc * 4);
            #pragma unroll
            for (int j = 0; j < 2; j++) {
                int idx = tid + j * 256;
                int lb = idx >> 3, xc = idx & 7;
                cpaCG(st + 2304 + lb * 144 + xc * 16,
                      &g_hB[lb >> 5][lb & 31][koff + xc * 4]);
            }
            CPC();
        };
        issueQ(0); issueQ(1);
        for (int c = 0; c < 16; c++) {
            if (c + 2 < 16) issueQ(c + 2); else CPC();
            CPW(2);
            __syncthreads();
            const float* wtf = (const float*)((char*)SMU + (c % 3) * 11520);
            const float* xtf = wtf + 576;   // +2304B
            #pragma unroll
            for (int ss = 0; ss < 4; ss++) {
                int s = kg * 4 + ss;
                u64 w0 = *(const u64*)(wtf + rpair * 36 + s * 2);
                u64 w1 = *(const u64*)(wtf + (rpair + 8) * 36 + s * 2);
                #pragma unroll
                for (int j = 0; j < 8; j++) {
                    u64 xv = *(const u64*)(xtf + (colg * 32 + 4 * j + bqi) * 36 + s * 2);
                    fma2(accA[j], xv, w0);
                    fma2(accB[j], xv, w1);
                }
            }
            __syncthreads();
        }
        CPW(0);
        {
            float* gp = (float*)SMU;   // [64][64]
            #pragma unroll
            for (int j = 0; j < 8; j++) {
                int cl = colg * 32 + 4 * j + bqi;
                gp[(kg * 16 + rpair) * 64 + cl]     = sum2(accA[j]);
                gp[(kg * 16 + rpair + 8) * 64 + cl] = sum2(accB[j]);
            }
            __syncthreads();
            #pragma unroll
            for (int i = 0; i < 4; i++) {
                int o = tid + i * 256;
                int r = o >> 6, cl = o & 63;
                float s = gp[r * 64 + cl] + gp[(16 + r) * 64 + cl]
                        + gp[(32 + r) * 64 + cl] + gp[(48 + r) * 64 + cl];
                g_q[cl][u0 + r] = tanhf(s + bq_[u0 + r]);
            }
            __threadfence();
            __syncthreads();
            if (tid == 0) atomicAdd(&g_qctr, 1);
        }
        // --- hatt: same tile shape, k=1024 in two halves, acc reused ---
        #pragma unroll
        for (int j = 0; j < 8; j++) { accA[j] = 0ull; accB[j] = 0ull; }
        for (int half = 0; half < 2; half++) {
            int wkoff = half ? 0 : 512;          // h-half first (k 512..1023)
            if (half == 1) {                      // attn data must be ready
                if (tid == 0) {
                    while (*(volatile int*)&g_attnctr < 32) __nanosleep(32);
                    __threadfence();
                }
                __syncthreads();
            }
            auto issueH = [&](int c) {
                char* st = (char*)SMU + (c % 3) * 11520;
                int koff = c * 32;
                if (w_act)
                    cpaCA(st + q_rl * 144 + q_wc * 16,
                          hattW + (size_t)(u0 + q_rl) * (2 * H) + wkoff + koff + q_wc * 4);
                #pragma unroll
                for (int j = 0; j < 2; j++) {
                    int idx = tid + j * 256;
                    int lb = idx >> 3, xc = idx & 7;
                    const float* src = half ? &g_attn[lb][koff + xc * 4]
                                            : &g_hB[lb >> 5][lb & 31][koff + xc * 4];
                    cpaCG(st + 2304 + lb * 144 + xc * 16, src);
                }
                CPC();
            };
            issueH(0); issueH(1);
            for (int c = 0; c < 16; c++) {
                if (c + 2 < 16) issueH(c + 2); else CPC();
                CPW(2);
                __syncthreads();
                const float* wtf = (const float*)((char*)SMU + (c % 3) * 11520);
                const float* xtf = wtf + 576;
                #pragma unroll
                for (int ss = 0; ss < 4; ss++) {
                    int s = kg * 4 + ss;
                    u64 w0 = *(const u64*)(wtf + rpair * 36 + s * 2);
                    u64 w1 = *(const u64*)(wtf + (rpair + 8) * 36 + s * 2);
                    #pragma unroll
                    for (int j = 0; j < 8; j++) {
                        u64 xv = *(const u64*)(xtf + (colg * 32 + 4 * j + bqi) * 36 + s * 2);
                        fma2(accA[j], xv, w0);
                        fma2(accB[j], xv, w1);
                    }
                }
                __syncthreads();
            }
            CPW(0);
        }
        {
            float* gp = (float*)SMU;
            #pragma unroll
            for (int j = 0; j < 8; j++) {
                int cl = colg * 32 + 4 * j + bqi;
                gp[(kg * 16 + rpair) * 64 + cl]     = sum2(accA[j]);
                gp[(kg * 16 + rpair + 8) * 64 + cl] = sum2(accB[j]);
            }
            __syncthreads();
            #pragma unroll
            for (int i = 0; i < 4; i++) {
                int o = tid + i * 256;
                int r = o >> 6, cl = o & 63;
                float s = gp[r * 64 + cl] + gp[(16 + r) * 64 + cl]
                        + gp[(32 + r) * 64 + cl] + gp[(48 + r) * 64 + cl];
                g_hA[cl >> 5][cl & 31][u0 + r] = tanhf(s + hattb[u0 + r]);
            }
        }
    } else if (bid < 143) {
        if (!doq) return;
        // ------------ attention: one b per block, both l ------------
        float* qs = (float*)SMU;           // [2][512]
        float* sc = qs + 1024;             // [2][64]
        int b = bid - 111;
        if (tid == 0) {
            while (*(volatile int*)&g_qctr < 32) __nanosleep(32);
            __threadfence();
        }
        __syncthreads();
        #pragma unroll
        for (int j = 0; j < 4; j++) {
            int idx = tid + j * 256;
            qs[idx] = __ldcg(&g_q[(idx >> 9) * 32 + b][idx & 511]);
        }
        __syncthreads();
        for (int d = wid; d < 2 * NS; d += 8) {
            int s = d >> 1, l = d & 1;
            const float* kr = &g_keysT[b][s][lane * 16];
            const float* qp = qs + l * 512 + lane * 16;
            u64 a = 0;
            #pragma unroll
            for (int t4 = 0; t4 < 4; t4++) {
                ulonglong2 kv = *(const ulonglong2*)(kr + t4 * 4);
                ulonglong2 qv = *(const ulonglong2*)(qp + t4 * 4);
                fma2(a, qv.x, kv.x);
                fma2(a, qv.y, kv.y);
            }
            float sv = wredsum(sum2(a));
            if (lane == 0) sc[l * 64 + s] = sv * (1.f / 7.f);
        }
        __syncthreads();
        if (tid < 2) {
            float* p = sc + tid * 64;
            float m = p[0];
            for (int s = 1; s < NS; s++) m = fmaxf(m, p[s]);
            float sum = 0.f;
            for (int s = 0; s < NS; s++) { float e = expf(p[s] - m); p[s] = e; sum += e; }
            float inv = 1.f / sum;
            for (int s = 0; s < NS; s++) p[s] *= inv;
        }
        __syncthreads();
        {
            int d2 = tid * 2;
            float a00 = 0.f, a01 = 0.f, a10 = 0.f, a11 = 0.f;
            for (int s = 0; s < NS; s++) {
                float2 v = *(const float2*)&g_valsT[b][s][d2];
                float w0 = sc[s], w1 = sc[64 + s];
                a00 += w0 * v.x; a01 += w0 * v.y;
                a10 += w1 * v.x; a11 += w1 * v.y;
            }
            *(float2*)&g_attn[b][d2]      = make_float2(a00, a01);
            *(float2*)&g_attn[32 + b][d2] = make_float2(a10, a11);
        }
        __threadfence();
        __syncthreads();
        if (tid == 0) atomicAdd(&g_attnctr, 1);
    }
    // bid >= 143: idle
}

// ---------------- launch ----------------
extern "C" void kernel_launch(void* const* d_in, const int* in_sizes, int n_in,
                              void* d_out, int out_size)
{
    const float* chan   = (const float*)d_in[0];
    const float* pooled = (const float*)d_in[1];
    const float* embed  = (const float*)d_in[2];
    const float* Wq     = (const float*)d_in[3];
    const float* bq     = (const float*)d_in[4];
    const float* Wk     = (const float*)d_in[5];
    const float* bk     = (const float*)d_in[6];
    const float* Wv     = (const float*)d_in[7];
    const float* bv     = (const float*)d_in[8];
    const float* Wih    = (const float*)d_in[9];
    const float* Whh    = (const float*)d_in[10];
    const float* bih    = (const float*)d_in[11];
    const float* bhh    = (const float*)d_in[12];
    const float* projW  = (const float*)d_in[13];
    const float* projb  = (const float*)d_in[14];
    const float* hattW  = (const float*)d_in[15];
    const float* hattb  = (const float*)d_in[16];
    const int*   sos    = (const int*)d_in[17];
    float* res = (float*)d_out;

    kPrepState<<<192, 256>>>(chan, Wk, bk, Wv, bv, pooled, sos);
    // res[:, :, 0] from <SOS> embedding (g_amax holds sos; logits only)
    kStep<<<148, 256>>>(1, embed, projW, projb, Wq, bq, hattW, hattb, res, 0, 0, 0);

    for (int t = 0; t < NT - 1; t++) {
        kLstm2<<<NBLK2, 256>>>(embed, Wih, Whh, bih, bhh);
        int last = (t == NT - 2);
        kStep<<<148, 256>>>(0, embed, projW, projb, Wq, bq, hattW, hattb,
                            res, t + 1, last ? 0 : 1, last ? 0 : 1);
    }
}